// round 5
// baseline (speedup 1.0000x reference)
#include <cuda_runtime.h>
#include <cuda_bf16.h>
#include <mma.h>
#include <math.h>
#include <cstdint>

using namespace nvcuda;

#define N_TOK   8192
#define DMODEL  256
#define NEXP    16
#define NVIEW   3
#define TOPK    4
#define HDIM    1024
#define ASSIGN_TOTAL (NVIEW * N_TOK * TOPK)
#define CAP     ASSIGN_TOTAL
#define TPB     256
#define BM      128
#define NCHUNK  16
#define TPB5    512

#define TILE_ELEMS 16384   /* 256x64 bf16 per chunk per tensor */

/* dynamic SMEM layout (bytes) */
#define XHI_OFF 0                        /* [128][264] bf16 = 67584 */
#define XLO_OFF 67584
#define W_OFF   135168                   /* 3 x 18432 cp.async ring  */
#define SLOT_BYTES 18432
#define H_OFF   190464                   /* Hhi[128][72] + Hlo, also fp32 scr */
#define SM_TOTAL 227328

/* ------------- static device scratch ------------- */
__device__ __nv_bfloat16 g_w1hi[NEXP * NCHUNK * TILE_ELEMS];
__device__ __nv_bfloat16 g_w1lo[NEXP * NCHUNK * TILE_ELEMS];
__device__ __nv_bfloat16 g_w2hi[NEXP * NCHUNK * TILE_ELEMS];
__device__ __nv_bfloat16 g_w2lo[NEXP * NCHUNK * TILE_ELEMS];
__device__ float g_comb[NVIEW * NEXP * DMODEL];
__device__ float g_kn2[NEXP];
__device__ int   g_cnt[NEXP];
__device__ int2  g_bucket[NEXP * CAP];

__device__ __forceinline__ uint32_t s2u(const void* p) {
    uint32_t a;
    asm("{ .reg .u64 t; cvta.to.shared.u64 t, %1; cvt.u32.u64 %0, t; }" : "=r"(a) : "l"(p));
    return a;
}
__device__ __forceinline__ uint32_t pack_hi_lo(float a0, float a1, uint32_t& lo) {
    __nv_bfloat16 h0 = __float2bfloat16_rn(a0), h1 = __float2bfloat16_rn(a1);
    float l0 = a0 - __bfloat162float(h0), l1 = a1 - __bfloat162float(h1);
    lo = ((uint32_t)__bfloat16_as_ushort(__float2bfloat16_rn(l1)) << 16)
       | (uint32_t)__bfloat16_as_ushort(__float2bfloat16_rn(l0));
    return ((uint32_t)__bfloat16_as_ushort(h1) << 16) | (uint32_t)__bfloat16_as_ushort(h0);
}
__device__ __forceinline__ float gelu_exact(float x) {
    return 0.5f * x * (1.0f + erff(x * 0.70710678118654752f));
}

/* ---------------- kernels 0-2: zero / router prep / gate ------------- */
__global__ void zero_kernel(float* __restrict__ out) {
    int i = blockIdx.x * blockDim.x + threadIdx.x;
    if (i < N_TOK * DMODEL) out[i] = 0.0f;
    if (i < NEXP) g_cnt[i] = 0;
}
__global__ void prep_kernel(const float* __restrict__ rw, const float* __restrict__ ek) {
    int t = threadIdx.x, lane = t & 31, w = t >> 5;
    for (int e = w; e < NEXP; e += 8) {
        float s = 0.f;
        #pragma unroll
        for (int j = 0; j < DMODEL; j += 32) { float x = ek[e * DMODEL + lane + j]; s += x * x; }
        #pragma unroll
        for (int o = 16; o; o >>= 1) s += __shfl_xor_sync(0xffffffffu, s, o);
        if (lane == 0) g_kn2[e] = s;
    }
    for (int i = t; i < NVIEW * NEXP * DMODEL; i += TPB) {
        int e = (i >> 8) & 15, d = i & 255;
        g_comb[i] = 2.0f * ek[e * DMODEL + d] + rw[i];
    }
}
__global__ __launch_bounds__(TPB) void gate_kernel(const float* __restrict__ v0,
                                                   const float* __restrict__ v1,
                                                   const float* __restrict__ v2) {
    __shared__ float scomb[NEXP * DMODEL];   /* 16KB: this block's view */
    __shared__ float skn2[NEXP];
    int t = threadIdx.x;
    int wg = (blockIdx.x * blockDim.x + t) >> 5;
    int lane = t & 31;
    int view = (int)((blockIdx.x * 8) >> 13);    /* uniform per block (8192%8==0) */
    {
        const float* cb = g_comb + view * NEXP * DMODEL;
        for (int i = t; i < NEXP * DMODEL; i += TPB) scomb[i] = cb[i];
        if (t < NEXP) skn2[t] = g_kn2[t];
    }
    __syncthreads();
    int tok = wg & (N_TOK - 1);
    const float* vp = (view == 0 ? v0 : (view == 1 ? v1 : v2)) + (size_t)tok * DMODEL;
    float xr[8];
    #pragma unroll
    for (int j = 0; j < 8; j++) xr[j] = vp[lane + 32 * j];
    float lg[NEXP];
    #pragma unroll
    for (int e = 0; e < NEXP; e++) {
        float p = 0.f;
        #pragma unroll
        for (int j = 0; j < 8; j++) p += xr[j] * scomb[e * DMODEL + lane + 32 * j];
        #pragma unroll
        for (int o = 16; o; o >>= 1) p += __shfl_xor_sync(0xffffffffu, p, o);
        lg[e] = p - skn2[e];
    }
    if (lane == 0) {
        float tv[TOPK]; int ti[TOPK]; unsigned used = 0;
        #pragma unroll
        for (int k = 0; k < TOPK; k++) {
            float best = -3.0e38f; int bi = 0;
            #pragma unroll
            for (int e = 0; e < NEXP; e++)
                if (!((used >> e) & 1u) && lg[e] > best) { best = lg[e]; bi = e; }
            used |= 1u << bi; tv[k] = best; ti[k] = bi;
        }
        float mx = tv[0], ex[TOPK], s = 0.f;
        #pragma unroll
        for (int k = 0; k < TOPK; k++) { ex[k] = expf(tv[k] - mx); s += ex[k]; }
        float inv = 1.0f / s;
        #pragma unroll
        for (int k = 0; k < TOPK; k++) {
            int e = ti[k];
            int slot = atomicAdd(&g_cnt[e], 1);
            g_bucket[e * CAP + slot] = make_int2(wg, __float_as_int(ex[k] * inv));
        }
    }
}

/* -------- kernel 3: split weights to bf16 hi/lo in MMA-ready [k][n] order ------ */
__global__ __launch_bounds__(TPB) void wprep_kernel(const float* __restrict__ W1,
                                                    const float* __restrict__ W2) {
    int e = blockIdx.x, c = blockIdx.y, z = blockIdx.z, t = threadIdx.x;
    size_t base = (size_t)(e * NCHUNK + c) * TILE_ELEMS;
    if (z == 0) {
        for (int idx = t; idx < TILE_ELEMS; idx += TPB) {
            int k = idx >> 6, n = idx & 63;
            float v = W1[(size_t)e * 262144 + (size_t)k * 1024 + c * 64 + n];
            __nv_bfloat16 hi = __float2bfloat16_rn(v);
            g_w1hi[base + idx] = hi;
            g_w1lo[base + idx] = __float2bfloat16_rn(v - __bfloat162float(hi));
        }
    } else {
        for (int idx = t; idx < TILE_ELEMS; idx += TPB) {
            int k = idx >> 8, n = idx & 255;
            float v = W2[(size_t)e * 262144 + (size_t)(c * 64 + k) * 256 + n];
            __nv_bfloat16 hi = __float2bfloat16_rn(v);
            g_w2hi[base + idx] = hi;
            g_w2lo[base + idx] = __float2bfloat16_rn(v - __bfloat162float(hi));
        }
    }
}

/* ---------------- kernel 4: WMMA grouped fused MLP, cp.async ring ---------------- */
typedef wmma::fragment<wmma::matrix_a, 16, 16, 16, __nv_bfloat16, wmma::row_major> FragA;
typedef wmma::fragment<wmma::matrix_b, 16, 16, 16, __nv_bfloat16, wmma::row_major> FragB;
typedef wmma::fragment<wmma::accumulator, 16, 16, 16, float> FragC;

/* sub-phase p (0..127): chunk c = p>>3, sub = p&7.
   sub 0..3: W1 (half = (sub>>1)&1, lo = sub&1), 128k x 64n, pitch 72
   sub 4..7: W2 (half = (sub-4)>>1, lo = sub&1), 32k x 256n, pitch 264     */
__device__ __forceinline__ void prefetch_phase(
    int p, int t, uint32_t smb,
    const __nv_bfloat16* w1h, const __nv_bfloat16* w1l,
    const __nv_bfloat16* w2h, const __nv_bfloat16* w2l)
{
    if (p < NCHUNK * 8) {
        int c = p >> 3, sub = p & 7;
        uint32_t slot = smb + W_OFF + (uint32_t)(p % 3) * SLOT_BYTES;
        if (sub < 4) {
            int half = (sub >> 1) & 1, lo = sub & 1;
            const char* src = (const char*)((lo ? w1l : w1h) + ((size_t)c * 256 + half * 128) * 64);
            #pragma unroll
            for (int v = 0; v < 2; v++) {
                int u = t + TPB5 * v;
                uint32_t dst = slot + (uint32_t)(u >> 3) * 144 + (uint32_t)(u & 7) * 16;
                asm volatile("cp.async.cg.shared.global [%0], [%1], 16;"
                             :: "r"(dst), "l"(src + (size_t)u * 16) : "memory");
            }
        } else {
            int half = (sub - 4) >> 1, lo = sub & 1;
            const char* src = (const char*)((lo ? w2l : w2h) + ((size_t)c * 64 + half * 32) * 256);
            #pragma unroll
            for (int v = 0; v < 2; v++) {
                int u = t + TPB5 * v;
                uint32_t dst = slot + (uint32_t)(u >> 5) * 528 + (uint32_t)(u & 31) * 16;
                asm volatile("cp.async.cg.shared.global [%0], [%1], 16;"
                             :: "r"(dst), "l"(src + (size_t)u * 16) : "memory");
            }
        }
    }
    asm volatile("cp.async.commit_group;" ::: "memory");
}

#define SP_BEGIN(p) do {                                             \
    asm volatile("cp.async.wait_group 1;" ::: "memory");             \
    __syncthreads();                                                 \
    prefetch_phase((p) + 2, t, smb, w1h, w1l, w2h, w2l);             \
} while (0)

__global__ __launch_bounds__(TPB5, 1)
void mlp_mma(const float* __restrict__ v0, const float* __restrict__ v1,
             const float* __restrict__ v2,
             const float* __restrict__ b1, const float* __restrict__ b2,
             float* __restrict__ out) {
    int e = blockIdx.y;
    int cnt = g_cnt[e];
    int r0 = blockIdx.x * BM;
    if (r0 >= cnt) return;

    extern __shared__ char dyn[];
    uint32_t smb = s2u(dyn);
    __nv_bfloat16* Xhi = (__nv_bfloat16*)(dyn + XHI_OFF);
    __nv_bfloat16* Xlo = (__nv_bfloat16*)(dyn + XLO_OFF);
    __nv_bfloat16* Hhi = (__nv_bfloat16*)(dyn + H_OFF);
    __nv_bfloat16* Hlo = (__nv_bfloat16*)(dyn + H_OFF + 18432);
    float*         scr = (float*)(dyn + H_OFF);        /* 128x68 fp32 = 34816 */

    __shared__ const float* s_ptr[BM];
    __shared__ float        s_gate[BM];
    __shared__ int          s_tok[BM];

    int t = threadIdx.x;
    const __nv_bfloat16* w1h = g_w1hi + (size_t)e * NCHUNK * TILE_ELEMS;
    const __nv_bfloat16* w1l = g_w1lo + (size_t)e * NCHUNK * TILE_ELEMS;
    const __nv_bfloat16* w2h = g_w2hi + (size_t)e * NCHUNK * TILE_ELEMS;
    const __nv_bfloat16* w2l = g_w2lo + (size_t)e * NCHUNK * TILE_ELEMS;

    /* start the ring immediately: phases 0 and 1 in flight */
    prefetch_phase(0, t, smb, w1h, w1l, w2h, w2l);
    prefetch_phase(1, t, smb, w1h, w1l, w2h, w2l);

    if (t < BM) {
        int gr = r0 + t;
        if (gr < cnt) {
            int2 rec = g_bucket[e * CAP + gr];
            int view = rec.x >> 13, tok = rec.x & (N_TOK - 1);
            s_ptr[t] = (view == 0 ? v0 : (view == 1 ? v1 : v2)) + (size_t)tok * DMODEL;
            s_tok[t] = tok; s_gate[t] = __int_as_float(rec.y);
        } else { s_ptr[t] = v0; s_tok[t] = 0; s_gate[t] = 0.f; }
    }
    __syncthreads();

    /* stage X split: thread t -> row t>>2, 64-col quarter t&3 */
    {
        int m = t >> 2, q = t & 3;
        const float4* src = (const float4*)(s_ptr[m] + q * 64);
        uint32_t* dh = (uint32_t*)&Xhi[m * 264 + q * 64];
        uint32_t* dl = (uint32_t*)&Xlo[m * 264 + q * 64];
        #pragma unroll
        for (int j = 0; j < 16; j++) {
            float4 f = src[j];
            uint32_t l01, l23;
            uint32_t h01 = pack_hi_lo(f.x, f.y, l01);
            uint32_t h23 = pack_hi_lo(f.z, f.w, l23);
            dh[2 * j] = h01; dh[2 * j + 1] = h23;
            dl[2 * j] = l01; dl[2 * j + 1] = l23;
        }
    }

    int wid = t >> 5;
    int wm = wid >> 2, wn = wid & 3;     /* 4x4 warp grid */

    FragC c2[2][4];
    #pragma unroll
    for (int i = 0; i < 2; i++)
        #pragma unroll
        for (int n = 0; n < 4; n++) wmma::fill_fragment(c2[i][n], 0.0f);

    for (int c = 0; c < NCHUNK; c++) {
        int pb = c * 8;
        FragC c1[2];
        wmma::fill_fragment(c1[0], 0.0f);
        wmma::fill_fragment(c1[1], 0.0f);

        /* ---- GEMM1: two k-halves, each hi-pass (2 mma) then lo-pass (1 mma) ---- */
        #pragma unroll
        for (int h = 0; h < 2; h++) {
            int k0 = h * 128;
            SP_BEGIN(pb + 2 * h);
            {
                const __nv_bfloat16* Ws = (const __nv_bfloat16*)(dyn + W_OFF + ((pb + 2 * h) % 3) * SLOT_BYTES);
                #pragma unroll
                for (int ks = 0; ks < 8; ks++) {
                    FragB bh;
                    wmma::load_matrix_sync(bh, Ws + ks * 16 * 72 + wn * 16, 72);
                    #pragma unroll
                    for (int i = 0; i < 2; i++) {
                        FragA a;
                        wmma::load_matrix_sync(a, Xhi + (wm * 32 + i * 16) * 264 + k0 + ks * 16, 264);
                        wmma::mma_sync(c1[i], a, bh, c1[i]);
                        wmma::load_matrix_sync(a, Xlo + (wm * 32 + i * 16) * 264 + k0 + ks * 16, 264);
                        wmma::mma_sync(c1[i], a, bh, c1[i]);
                    }
                }
            }
            SP_BEGIN(pb + 2 * h + 1);
            {
                const __nv_bfloat16* Ws = (const __nv_bfloat16*)(dyn + W_OFF + ((pb + 2 * h + 1) % 3) * SLOT_BYTES);
                #pragma unroll
                for (int ks = 0; ks < 8; ks++) {
                    FragB bl;
                    wmma::load_matrix_sync(bl, Ws + ks * 16 * 72 + wn * 16, 72);
                    #pragma unroll
                    for (int i = 0; i < 2; i++) {
                        FragA a;
                        wmma::load_matrix_sync(a, Xhi + (wm * 32 + i * 16) * 264 + k0 + ks * 16, 264);
                        wmma::mma_sync(c1[i], a, bl, c1[i]);
                    }
                }
            }
        }

        /* ---- bias + gelu + split (scr shares H region: read-all then write) ---- */
        wmma::store_matrix_sync(&scr[(wm * 32) * 68 + wn * 16], c1[0], 68, wmma::mem_row_major);
        wmma::store_matrix_sync(&scr[(wm * 32 + 16) * 68 + wn * 16], c1[1], 68, wmma::mem_row_major);
        __syncthreads();
        float hv[16];
        {
            int m = t >> 2, q = t & 3;
            const float* bb = b1 + e * HDIM + c * 64 + q * 16;
            #pragma unroll
            for (int j = 0; j < 16; j++)
                hv[j] = gelu_exact(scr[m * 68 + q * 16 + j] + __ldg(bb + j));
        }
        __syncthreads();
        {
            int m = t >> 2, q = t & 3;
            uint32_t* dh = (uint32_t*)&Hhi[m * 72 + q * 16];
            uint32_t* dl = (uint32_t*)&Hlo[m * 72 + q * 16];
            #pragma unroll
            for (int j = 0; j < 8; j++) {
                uint32_t lo;
                dh[j] = pack_hi_lo(hv[2 * j], hv[2 * j + 1], lo);
                dl[j] = lo;
            }
        }

        /* ---- GEMM2: two k-halves of 32, hi-pass then lo-pass ---- */
        #pragma unroll
        for (int h = 0; h < 2; h++) {
            int kb = h * 32;
            SP_BEGIN(pb + 4 + 2 * h);
            {
                const __nv_bfloat16* Ws = (const __nv_bfloat16*)(dyn + W_OFF + ((pb + 4 + 2 * h) % 3) * SLOT_BYTES);
                #pragma unroll
                for (int ks = 0; ks < 2; ks++) {
                    #pragma unroll
                    for (int i = 0; i < 2; i++) {
                        FragA ah, al;
                        wmma::load_matrix_sync(ah, Hhi + (wm * 32 + i * 16) * 72 + kb + ks * 16, 72);
                        wmma::load_matrix_sync(al, Hlo + (wm * 32 + i * 16) * 72 + kb + ks * 16, 72);
                        #pragma unroll
                        for (int nf = 0; nf < 4; nf++) {
                            FragB b;
                            wmma::load_matrix_sync(b, Ws + ks * 16 * 264 + wn * 64 + nf * 16, 264);
                            wmma::mma_sync(c2[i][nf], ah, b, c2[i][nf]);
                            wmma::mma_sync(c2[i][nf], al, b, c2[i][nf]);
                        }
                    }
                }
            }
            SP_BEGIN(pb + 4 + 2 * h + 1);
            {
                const __nv_bfloat16* Ws = (const __nv_bfloat16*)(dyn + W_OFF + ((pb + 4 + 2 * h + 1) % 3) * SLOT_BYTES);
                #pragma unroll
                for (int ks = 0; ks < 2; ks++) {
                    #pragma unroll
                    for (int i = 0; i < 2; i++) {
                        FragA ah;
                        wmma::load_matrix_sync(ah, Hhi + (wm * 32 + i * 16) * 72 + kb + ks * 16, 72);
                        #pragma unroll
                        for (int nf = 0; nf < 4; nf++) {
                            FragB b;
                            wmma::load_matrix_sync(b, Ws + ks * 16 * 264 + wn * 64 + nf * 16, 264);
                            wmma::mma_sync(c2[i][nf], ah, b, c2[i][nf]);
                        }
                    }
                }
            }
        }
    }

    /* ---- epilogue: C2 -> out (gate, +b2) via scr in 4 column-quarters ---- */
    #pragma unroll
    for (int q = 0; q < 4; q++) {
        __syncthreads();
        if (wn == q) {
            #pragma unroll
            for (int i = 0; i < 2; i++)
                #pragma unroll
                for (int nf = 0; nf < 4; nf++)
                    wmma::store_matrix_sync(&scr[(wm * 32 + i * 16) * 68 + nf * 16],
                                            c2[i][nf], 68, wmma::mem_row_major);
        }
        __syncthreads();
        int m = t >> 2, cq = t & 3;
        float g = s_gate[m];
        if (g != 0.f) {
            int tok = s_tok[m];
            int nbase = q * 64 + cq * 16;
            #pragma unroll
            for (int j = 0; j < 16; j++) {
                int n = nbase + j;
                atomicAdd(&out[(size_t)tok * DMODEL + n],
                          g * (scr[m * 68 + cq * 16 + j] + __ldg(&b2[e * DMODEL + n])));
            }
        }
    }
}

/* ---------------- launch ---------------- */
extern "C" void kernel_launch(void* const* d_in, const int* in_sizes, int n_in,
                              void* d_out, int out_size) {
    const float* v0 = (const float*)d_in[0];
    const float* v1 = (const float*)d_in[1];
    const float* v2 = (const float*)d_in[2];
    const float* rw = (const float*)d_in[3];
    const float* ek = (const float*)d_in[4];
    const float* W1 = (const float*)d_in[5];
    const float* b1 = (const float*)d_in[6];
    const float* W2 = (const float*)d_in[7];
    const float* b2 = (const float*)d_in[8];
    float* out = (float*)d_out;

    cudaFuncSetAttribute(mlp_mma, cudaFuncAttributeMaxDynamicSharedMemorySize, SM_TOTAL);

    zero_kernel<<<(N_TOK * DMODEL + TPB - 1) / TPB, TPB>>>(out);
    prep_kernel<<<1, TPB>>>(rw, ek);
    wprep_kernel<<<dim3(NEXP, NCHUNK, 2), TPB>>>(W1, W2);
    gate_kernel<<<(NVIEW * N_TOK * 32) / TPB, TPB>>>(v0, v1, v2);

    dim3 grid(ASSIGN_TOTAL / BM, NEXP);
    mlp_mma<<<grid, TPB5, SM_TOTAL>>>(v0, v1, v2, b1, b2, out);
}

// round 6
// speedup vs baseline: 2.2928x; 2.2928x over previous
#include <cuda_runtime.h>
#include <cuda_fp16.h>
#include <mma.h>
#include <math.h>
#include <cstdint>

using namespace nvcuda;

#define N_TOK   8192
#define DMODEL  256
#define NEXP    16
#define NVIEW   3
#define TOPK    4
#define HDIM    1024
#define ASSIGN_TOTAL (NVIEW * N_TOK * TOPK)
#define CAP     ASSIGN_TOTAL
#define TPB     256
#define BM      128
#define NCHUNK  16
#define TPB5    512

#define TILE_ELEMS 16384   /* 256x64 (or 64x256) fp16 per chunk */

/* dynamic SMEM layout (bytes) */
#define XH_OFF  0                        /* X fp16 [128][264]  = 67584 */
#define W_OFF   67584                    /* 3 x 18432 cp.async ring    */
#define SLOT_BYTES 18432
#define H_OFF   122880                   /* H fp16 [128][72]   = 18432 */
#define SCR_OFF 141312                   /* fp32 scr [128][68] = 34816 */
#define SM_TOTAL 176128

/* ------------- static device scratch ------------- */
__device__ __half g_w1[NEXP * NCHUNK * TILE_ELEMS];
__device__ __half g_w2[NEXP * NCHUNK * TILE_ELEMS];
__device__ float g_comb[NVIEW * NEXP * DMODEL];
__device__ float g_kn2[NEXP];
__device__ int   g_cnt[NEXP];
__device__ int2  g_bucket[NEXP * CAP];

__device__ __forceinline__ uint32_t s2u(const void* p) {
    uint32_t a;
    asm("{ .reg .u64 t; cvta.to.shared.u64 t, %1; cvt.u32.u64 %0, t; }" : "=r"(a) : "l"(p));
    return a;
}
__device__ __forceinline__ float gelu_exact(float x) {
    return 0.5f * x * (1.0f + erff(x * 0.70710678118654752f));
}

/* ---------------- kernels 0-2: zero / router prep / gate (proven) ------------- */
__global__ void zero_kernel(float* __restrict__ out) {
    int i = blockIdx.x * blockDim.x + threadIdx.x;
    if (i < N_TOK * DMODEL) out[i] = 0.0f;
    if (i < NEXP) g_cnt[i] = 0;
}
__global__ void prep_kernel(const float* __restrict__ rw, const float* __restrict__ ek) {
    int t = threadIdx.x, lane = t & 31, w = t >> 5;
    for (int e = w; e < NEXP; e += 8) {
        float s = 0.f;
        #pragma unroll
        for (int j = 0; j < DMODEL; j += 32) { float x = ek[e * DMODEL + lane + j]; s += x * x; }
        #pragma unroll
        for (int o = 16; o; o >>= 1) s += __shfl_xor_sync(0xffffffffu, s, o);
        if (lane == 0) g_kn2[e] = s;
    }
    for (int i = t; i < NVIEW * NEXP * DMODEL; i += TPB) {
        int e = (i >> 8) & 15, d = i & 255;
        g_comb[i] = 2.0f * ek[e * DMODEL + d] + rw[i];
    }
}
__global__ __launch_bounds__(TPB) void gate_kernel(const float* __restrict__ v0,
                                                   const float* __restrict__ v1,
                                                   const float* __restrict__ v2) {
    __shared__ float scomb[NEXP * DMODEL];
    __shared__ float skn2[NEXP];
    int t = threadIdx.x;
    int wg = (blockIdx.x * blockDim.x + t) >> 5;
    int lane = t & 31;
    int view = (int)((blockIdx.x * 8) >> 13);
    {
        const float* cb = g_comb + view * NEXP * DMODEL;
        for (int i = t; i < NEXP * DMODEL; i += TPB) scomb[i] = cb[i];
        if (t < NEXP) skn2[t] = g_kn2[t];
    }
    __syncthreads();
    int tok = wg & (N_TOK - 1);
    const float* vp = (view == 0 ? v0 : (view == 1 ? v1 : v2)) + (size_t)tok * DMODEL;
    float xr[8];
    #pragma unroll
    for (int j = 0; j < 8; j++) xr[j] = vp[lane + 32 * j];
    float lg[NEXP];
    #pragma unroll
    for (int e = 0; e < NEXP; e++) {
        float p = 0.f;
        #pragma unroll
        for (int j = 0; j < 8; j++) p += xr[j] * scomb[e * DMODEL + lane + 32 * j];
        #pragma unroll
        for (int o = 16; o; o >>= 1) p += __shfl_xor_sync(0xffffffffu, p, o);
        lg[e] = p - skn2[e];
    }
    if (lane == 0) {
        float tv[TOPK]; int ti[TOPK]; unsigned used = 0;
        #pragma unroll
        for (int k = 0; k < TOPK; k++) {
            float best = -3.0e38f; int bi = 0;
            #pragma unroll
            for (int e = 0; e < NEXP; e++)
                if (!((used >> e) & 1u) && lg[e] > best) { best = lg[e]; bi = e; }
            used |= 1u << bi; tv[k] = best; ti[k] = bi;
        }
        float mx = tv[0], ex[TOPK], s = 0.f;
        #pragma unroll
        for (int k = 0; k < TOPK; k++) { ex[k] = expf(tv[k] - mx); s += ex[k]; }
        float inv = 1.0f / s;
        #pragma unroll
        for (int k = 0; k < TOPK; k++) {
            int e = ti[k];
            int slot = atomicAdd(&g_cnt[e], 1);
            g_bucket[e * CAP + slot] = make_int2(wg, __float_as_int(ex[k] * inv));
        }
    }
}

/* -------- kernel 3: convert weights to fp16 in MMA-ready [k][n] chunk order ------ */
__global__ __launch_bounds__(TPB) void wprep_kernel(const float* __restrict__ W1,
                                                    const float* __restrict__ W2) {
    int e = blockIdx.x, c = blockIdx.y, z = blockIdx.z, t = threadIdx.x;
    size_t base = (size_t)(e * NCHUNK + c) * TILE_ELEMS;
    if (z == 0) {
        for (int idx = t; idx < TILE_ELEMS; idx += TPB) {
            int k = idx >> 6, n = idx & 63;
            g_w1[base + idx] = __float2half_rn(W1[(size_t)e * 262144 + (size_t)k * 1024 + c * 64 + n]);
        }
    } else {
        for (int idx = t; idx < TILE_ELEMS; idx += TPB) {
            int k = idx >> 8, n = idx & 255;
            g_w2[base + idx] = __float2half_rn(W2[(size_t)e * 262144 + (size_t)(c * 64 + k) * 256 + n]);
        }
    }
}

/* ---------------- kernel 4: fp16 WMMA grouped fused MLP, cp.async ring ---------------- */
typedef wmma::fragment<wmma::matrix_a, 16, 16, 16, __half, wmma::row_major> FragA;
typedef wmma::fragment<wmma::matrix_b, 16, 16, 16, __half, wmma::row_major> FragB;
typedef wmma::fragment<wmma::accumulator, 16, 16, 16, float> FragC;

/* sub-phase p (0..63): chunk c = p>>2, sub = p&3.
   sub 0/1: W1 k-half sub     (128k x 64n,  pitch 72 halves / 144 B)
   sub 2/3: W2 k-half (sub-2) ( 32k x 256n, pitch 264 halves / 528 B)   */
__device__ __forceinline__ void prefetch_phase(
    int p, int t, uint32_t smb, const __half* w1, const __half* w2)
{
    if (p < NCHUNK * 4) {
        int c = p >> 2, sub = p & 3;
        uint32_t slot = smb + W_OFF + (uint32_t)(p % 3) * SLOT_BYTES;
        if (sub < 2) {
            const char* src = (const char*)(w1 + ((size_t)c * 256 + sub * 128) * 64);
            #pragma unroll
            for (int v = 0; v < 2; v++) {
                int u = t + TPB5 * v;                 /* 0..1023 16B units */
                uint32_t dst = slot + (uint32_t)(u >> 3) * 144 + (uint32_t)(u & 7) * 16;
                asm volatile("cp.async.cg.shared.global [%0], [%1], 16;"
                             :: "r"(dst), "l"(src + (size_t)u * 16) : "memory");
            }
        } else {
            const char* src = (const char*)(w2 + ((size_t)c * 64 + (sub - 2) * 32) * 256);
            #pragma unroll
            for (int v = 0; v < 2; v++) {
                int u = t + TPB5 * v;
                uint32_t dst = slot + (uint32_t)(u >> 5) * 528 + (uint32_t)(u & 31) * 16;
                asm volatile("cp.async.cg.shared.global [%0], [%1], 16;"
                             :: "r"(dst), "l"(src + (size_t)u * 16) : "memory");
            }
        }
    }
    asm volatile("cp.async.commit_group;" ::: "memory");
}

#define SP_BEGIN(p) do {                                             \
    asm volatile("cp.async.wait_group 1;" ::: "memory");             \
    __syncthreads();                                                 \
    prefetch_phase((p) + 2, t, smb, w1, w2);                         \
} while (0)

__global__ __launch_bounds__(TPB5, 1)
void mlp_mma(const float* __restrict__ v0, const float* __restrict__ v1,
             const float* __restrict__ v2,
             const float* __restrict__ b1, const float* __restrict__ b2,
             float* __restrict__ out) {
    int e = blockIdx.y;
    int cnt = g_cnt[e];
    int r0 = blockIdx.x * BM;
    if (r0 >= cnt) return;

    extern __shared__ char dyn[];
    uint32_t smb = s2u(dyn);
    __half* Xh = (__half*)(dyn + XH_OFF);           /* [128][264] */
    __half* Hh = (__half*)(dyn + H_OFF);            /* [128][72]  */
    float*  scr = (float*)(dyn + SCR_OFF);          /* [128][68]  */

    __shared__ const float* s_ptr[BM];
    __shared__ float        s_gate[BM];
    __shared__ int          s_tok[BM];

    int t = threadIdx.x;
    const __half* w1 = g_w1 + (size_t)e * NCHUNK * TILE_ELEMS;
    const __half* w2 = g_w2 + (size_t)e * NCHUNK * TILE_ELEMS;

    /* start the ring: phases 0 and 1 in flight */
    prefetch_phase(0, t, smb, w1, w2);
    prefetch_phase(1, t, smb, w1, w2);

    if (t < BM) {
        int gr = r0 + t;
        if (gr < cnt) {
            int2 rec = g_bucket[e * CAP + gr];
            int view = rec.x >> 13, tok = rec.x & (N_TOK - 1);
            s_ptr[t] = (view == 0 ? v0 : (view == 1 ? v1 : v2)) + (size_t)tok * DMODEL;
            s_tok[t] = tok; s_gate[t] = __int_as_float(rec.y);
        } else { s_ptr[t] = v0; s_tok[t] = 0; s_gate[t] = 0.f; }
    }
    __syncthreads();

    /* stage X fp16: thread t -> row t>>2, 64-col quarter t&3 */
    {
        int m = t >> 2, q = t & 3;
        const float4* src = (const float4*)(s_ptr[m] + q * 64);
        uint32_t* dh = (uint32_t*)&Xh[m * 264 + q * 64];
        #pragma unroll
        for (int j = 0; j < 16; j++) {
            float4 f = src[j];
            __half2 a = __floats2half2_rn(f.x, f.y);
            __half2 b = __floats2half2_rn(f.z, f.w);
            dh[2 * j]     = *(uint32_t*)&a;
            dh[2 * j + 1] = *(uint32_t*)&b;
        }
    }

    int wid = t >> 5;
    int wm = wid >> 2, wn = wid & 3;     /* 4x4 warp grid */

    FragC c2[2][4];
    #pragma unroll
    for (int i = 0; i < 2; i++)
        #pragma unroll
        for (int n = 0; n < 4; n++) wmma::fill_fragment(c2[i][n], 0.0f);

    for (int c = 0; c < NCHUNK; c++) {
        int pb = c * 4;
        FragC c1[2];
        wmma::fill_fragment(c1[0], 0.0f);
        wmma::fill_fragment(c1[1], 0.0f);

        /* ---- GEMM1: C1[128][64] = X @ W1c, K=256 in 2 halves ---- */
        #pragma unroll
        for (int h = 0; h < 2; h++) {
            SP_BEGIN(pb + h);
            const __half* Ws = (const __half*)(dyn + W_OFF + ((pb + h) % 3) * SLOT_BYTES);
            #pragma unroll
            for (int ks = 0; ks < 8; ks++) {
                FragB b;
                wmma::load_matrix_sync(b, Ws + ks * 16 * 72 + wn * 16, 72);
                #pragma unroll
                for (int i = 0; i < 2; i++) {
                    FragA a;
                    wmma::load_matrix_sync(a, Xh + (wm * 32 + i * 16) * 264 + h * 128 + ks * 16, 264);
                    wmma::mma_sync(c1[i], a, b, c1[i]);
                }
            }
        }

        /* ---- bias + gelu -> H fp16 (scr is its own region) ---- */
        wmma::store_matrix_sync(&scr[(wm * 32) * 68 + wn * 16], c1[0], 68, wmma::mem_row_major);
        wmma::store_matrix_sync(&scr[(wm * 32 + 16) * 68 + wn * 16], c1[1], 68, wmma::mem_row_major);
        __syncthreads();
        {
            int m = t >> 2, q = t & 3;
            const float* bb = b1 + e * HDIM + c * 64 + q * 16;
            uint32_t* dh = (uint32_t*)&Hh[m * 72 + q * 16];
            #pragma unroll
            for (int j = 0; j < 8; j++) {
                float g0 = gelu_exact(scr[m * 68 + q * 16 + 2 * j]     + __ldg(bb + 2 * j));
                float g1 = gelu_exact(scr[m * 68 + q * 16 + 2 * j + 1] + __ldg(bb + 2 * j + 1));
                __half2 hp = __floats2half2_rn(g0, g1);
                dh[j] = *(uint32_t*)&hp;
            }
        }

        /* ---- GEMM2: C2[128][256] += H @ W2c, K=64 in 2 halves ---- */
        #pragma unroll
        for (int h = 0; h < 2; h++) {
            SP_BEGIN(pb + 2 + h);
            const __half* Ws = (const __half*)(dyn + W_OFF + ((pb + 2 + h) % 3) * SLOT_BYTES);
            #pragma unroll
            for (int ks = 0; ks < 2; ks++) {
                #pragma unroll
                for (int i = 0; i < 2; i++) {
                    FragA a;
                    wmma::load_matrix_sync(a, Hh + (wm * 32 + i * 16) * 72 + h * 32 + ks * 16, 72);
                    #pragma unroll
                    for (int nf = 0; nf < 4; nf++) {
                        FragB b;
                        wmma::load_matrix_sync(b, Ws + ks * 16 * 264 + wn * 64 + nf * 16, 264);
                        wmma::mma_sync(c2[i][nf], a, b, c2[i][nf]);
                    }
                }
            }
        }
    }

    /* ---- epilogue: C2 -> out (gate, +b2) via scr in 4 column-quarters ---- */
    #pragma unroll
    for (int q = 0; q < 4; q++) {
        __syncthreads();
        if (wn == q) {
            #pragma unroll
            for (int i = 0; i < 2; i++)
                #pragma unroll
                for (int nf = 0; nf < 4; nf++)
                    wmma::store_matrix_sync(&scr[(wm * 32 + i * 16) * 68 + nf * 16],
                                            c2[i][nf], 68, wmma::mem_row_major);
        }
        __syncthreads();
        int m = t >> 2, cq = t & 3;
        float g = s_gate[m];
        if (g != 0.f) {
            int tok = s_tok[m];
            int nbase = q * 64 + cq * 16;
            #pragma unroll
            for (int j = 0; j < 16; j++) {
                int n = nbase + j;
                atomicAdd(&out[(size_t)tok * DMODEL + n],
                          g * (scr[m * 68 + cq * 16 + j] + __ldg(&b2[e * DMODEL + n])));
            }
        }
    }
}

/* ---------------- launch ---------------- */
extern "C" void kernel_launch(void* const* d_in, const int* in_sizes, int n_in,
                              void* d_out, int out_size) {
    const float* v0 = (const float*)d_in[0];
    const float* v1 = (const float*)d_in[1];
    const float* v2 = (const float*)d_in[2];
    const float* rw = (const float*)d_in[3];
    const float* ek = (const float*)d_in[4];
    const float* W1 = (const float*)d_in[5];
    const float* b1 = (const float*)d_in[6];
    const float* W2 = (const float*)d_in[7];
    const float* b2 = (const float*)d_in[8];
    float* out = (float*)d_out;

    cudaFuncSetAttribute(mlp_mma, cudaFuncAttributeMaxDynamicSharedMemorySize, SM_TOTAL);

    zero_kernel<<<(N_TOK * DMODEL + TPB - 1) / TPB, TPB>>>(out);
    prep_kernel<<<1, TPB>>>(rw, ek);
    wprep_kernel<<<dim3(NEXP, NCHUNK, 2), TPB>>>(W1, W2);
    gate_kernel<<<(NVIEW * N_TOK * 32) / TPB, TPB>>>(v0, v1, v2);

    dim3 grid(ASSIGN_TOTAL / BM, NEXP);
    mlp_mma<<<grid, TPB5, SM_TOTAL>>>(v0, v1, v2, b1, b2, out);
}